// round 6
// baseline (speedup 1.0000x reference)
#include <cuda_runtime.h>
#include <cuda_fp16.h>

#define NPTS 500000
#define NCLS 20
#define RPAD 32      // padded row stride in halves (64 B, line-aligned)
#define NK   16

// fp16 probs table, 64B-padded rows: 500000*32*2B = 32 MB (L2-resident).
__device__ __half g_probs_h[(size_t)NPTS * RPAD];
__device__ float  g_acc[2];    // [0]=sum of mean_dist over valid pts, [1]=valid count
__device__ int    g_done = 0;

// Kernel 1: softmax (fp32 in, fp16 out, padded rows) + accumulator reset.
__global__ void softmax_kernel(const float* __restrict__ logits) {
    if (blockIdx.x == 0 && threadIdx.x == 0) {
        g_acc[0] = 0.0f;
        g_acc[1] = 0.0f;
        g_done   = 0;
    }
    int n = blockIdx.x * blockDim.x + threadIdx.x;
    if (n >= NPTS) return;
    const float4* src = reinterpret_cast<const float4*>(logits + (size_t)n * NCLS);
    float4 v[5];
#pragma unroll
    for (int i = 0; i < 5; i++) v[i] = src[i];
    float* f = reinterpret_cast<float*>(v);
    float m = f[0];
#pragma unroll
    for (int i = 1; i < NCLS; i++) m = fmaxf(m, f[i]);
    float s = 0.0f;
#pragma unroll
    for (int i = 0; i < NCLS; i++) { f[i] = __expf(f[i] - m); s += f[i]; }
    float inv = 1.0f / s;
    __half2* dst = reinterpret_cast<__half2*>(g_probs_h + (size_t)n * RPAD);
#pragma unroll
    for (int i = 0; i < 10; i++)
        dst[i] = __floats2half2_rn(f[2 * i] * inv, f[2 * i + 1] * inv);
}

// Kernel 2: warp-per-point gather, 3 points in flight per iteration (MLP x3).
// Lane layout: grp = lane>>3 (0..3), sub = lane&7; lanes with sub<5 own classes
// [4*sub,4*sub+4) as uint2 (two half2). Step s (0..3): group g handles neighbor
// 4*s+g -> one LDG.64 instruction gathers 4 neighbor rows, each row = 1 L1 line.
__global__ void loss_kernel(const int* __restrict__ nbr,
                            const int* __restrict__ labels,
                            float* __restrict__ out) {
    const int lane = threadIdx.x & 31;
    const int warpInBlock = threadIdx.x >> 5;
    const int warpsPerBlock = blockDim.x >> 5;
    const int gwarp = blockIdx.x * warpsPerBlock + warpInBlock;
    const int totalWarps = gridDim.x * warpsPerBlock;
    const int grp = lane >> 3;
    const int sub = lane & 7;
    const bool active = (sub < 5);
    const int laneOff = 4 * sub;   // half offset within a padded row

    float accTot = 0.0f;
    float cnt    = 0.0f;
    const __half2 z2 = __float2half2_rn(0.f);

    for (int n0 = gwarp; n0 < NPTS; n0 += 3 * totalWarps) {
        const int n1 = n0 + totalWarps;
        const int n2 = n0 + 2 * totalWarps;
        const bool has1 = (n1 < NPTS);
        const bool has2 = (n2 < NPTS);

        // ---- front loads for all three points ----
        int lab0 = labels[n0];
        int lab1 = has1 ? labels[n1] : -1;
        int lab2 = has2 ? labels[n2] : -1;

        int idx0 = -1, idx1 = -1, idx2 = -1;
        if (lane < NK) {
            idx0 = nbr[n0 * NK + lane];
            if (has1) idx1 = nbr[n1 * NK + lane];
            if (has2) idx2 = nbr[n2 * NK + lane];
        }

        __half2 pa0 = z2, pb0 = z2, pa1 = z2, pb1 = z2, pa2 = z2, pb2 = z2;
        if (active) {
            uint2 pw0 = *reinterpret_cast<const uint2*>(g_probs_h + (n0 << 5) + laneOff);
            pa0 = *reinterpret_cast<__half2*>(&pw0.x);
            pb0 = *reinterpret_cast<__half2*>(&pw0.y);
            if (has1) {
                uint2 pw1 = *reinterpret_cast<const uint2*>(g_probs_h + (n1 << 5) + laneOff);
                pa1 = *reinterpret_cast<__half2*>(&pw1.x);
                pb1 = *reinterpret_cast<__half2*>(&pw1.y);
            }
            if (has2) {
                uint2 pw2 = *reinterpret_cast<const uint2*>(g_probs_h + (n2 << 5) + laneOff);
                pa2 = *reinterpret_cast<__half2*>(&pw2.x);
                pb2 = *reinterpret_cast<__half2*>(&pw2.y);
            }
        }

        unsigned vm0 = __ballot_sync(0xFFFFFFFFu, (lane < NK) && (idx0 >= 0));
        unsigned vm1 = __ballot_sync(0xFFFFFFFFu, (lane < NK) && (idx1 >= 0));
        unsigned vm2 = __ballot_sync(0xFFFFFFFFu, (lane < NK) && (idx2 >= 0));
        int nv0 = __popc(vm0), nv1 = __popc(vm1), nv2 = __popc(vm2);
        bool do0 = (lab0 != -1) && nv0 > 0;
        bool do1 = has1 && (lab1 != -1) && nv1 > 0;
        bool do2 = has2 && (lab2 != -1) && nv2 > 0;

        // ---- shuffles, then all 12 gathers in flight ----
        int q0[4], q1[4], q2[4];
#pragma unroll
        for (int s = 0; s < 4; s++) {
            q0[s] = __shfl_sync(0xFFFFFFFFu, idx0, 4 * s + grp);
            q1[s] = __shfl_sync(0xFFFFFFFFu, idx1, 4 * s + grp);
            q2[s] = __shfl_sync(0xFFFFFFFFu, idx2, 4 * s + grp);
        }

        __half2 acc0 = z2, acc1 = z2, acc2 = z2;
#pragma unroll
        for (int s = 0; s < 4; s++) {
            if (do0 && active && q0[s] >= 0) {
                uint2 qw = *reinterpret_cast<const uint2*>(
                    g_probs_h + (q0[s] << 5) + laneOff);
                __half2 da = __hsub2(pa0, *reinterpret_cast<__half2*>(&qw.x));
                __half2 db = __hsub2(pb0, *reinterpret_cast<__half2*>(&qw.y));
                acc0 = __hfma2(da, da, acc0);
                acc0 = __hfma2(db, db, acc0);
            }
            if (do1 && active && q1[s] >= 0) {
                uint2 qw = *reinterpret_cast<const uint2*>(
                    g_probs_h + (q1[s] << 5) + laneOff);
                __half2 da = __hsub2(pa1, *reinterpret_cast<__half2*>(&qw.x));
                __half2 db = __hsub2(pb1, *reinterpret_cast<__half2*>(&qw.y));
                acc1 = __hfma2(da, da, acc1);
                acc1 = __hfma2(db, db, acc1);
            }
            if (do2 && active && q2[s] >= 0) {
                uint2 qw = *reinterpret_cast<const uint2*>(
                    g_probs_h + (q2[s] << 5) + laneOff);
                __half2 da = __hsub2(pa2, *reinterpret_cast<__half2*>(&qw.x));
                __half2 db = __hsub2(pb2, *reinterpret_cast<__half2*>(&qw.y));
                acc2 = __hfma2(da, da, acc2);
                acc2 = __hfma2(db, db, acc2);
            }
        }

        if (do0) {
            float2 af = __half22float2(acc0);
            accTot = fmaf(af.x + af.y, __frcp_rn((float)nv0), accTot);
        }
        if (do1) {
            float2 af = __half22float2(acc1);
            accTot = fmaf(af.x + af.y, __frcp_rn((float)nv1), accTot);
        }
        if (do2) {
            float2 af = __half22float2(acc2);
            accTot = fmaf(af.x + af.y, __frcp_rn((float)nv2), accTot);
        }
        cnt += (lab0 != -1 ? 1.0f : 0.0f)
             + (has1 && lab1 != -1 ? 1.0f : 0.0f)
             + (has2 && lab2 != -1 ? 1.0f : 0.0f);
    }

    // One butterfly reduce per warp
#pragma unroll
    for (int o = 16; o > 0; o >>= 1)
        accTot += __shfl_xor_sync(0xFFFFFFFFu, accTot, o);

    // Block reduce -> one atomic pair per block
    __shared__ float sSum[32];
    __shared__ float sCnt[32];
    if (lane == 0) { sSum[warpInBlock] = accTot; sCnt[warpInBlock] = cnt; }
    __syncthreads();
    if (threadIdx.x == 0) {
        float bs = 0.0f, bc = 0.0f;
        for (int w = 0; w < warpsPerBlock; w++) { bs += sSum[w]; bc += sCnt[w]; }
        atomicAdd(&g_acc[0], bs);
        atomicAdd(&g_acc[1], bc);
        __threadfence();
        int t = atomicAdd(&g_done, 1);
        if (t == gridDim.x - 1) {
            out[0] = g_acc[0] / fmaxf(g_acc[1], 1.0f);  // LOSS_WEIGHT = 1.0
            g_done = 0;
        }
    }
}

extern "C" void kernel_launch(void* const* d_in, const int* in_sizes, int n_in,
                              void* d_out, int out_size) {
    const float* logits = nullptr;
    const int*   nbr    = nullptr;
    const int*   labels = nullptr;
    for (int i = 0; i < n_in; i++) {
        if (in_sizes[i] == NPTS * NCLS)    logits = (const float*)d_in[i];
        else if (in_sizes[i] == NPTS * NK) nbr    = (const int*)d_in[i];
        else if (in_sizes[i] == NPTS)      labels = (const int*)d_in[i];
    }
    float* out = (float*)d_out;

    softmax_kernel<<<(NPTS + 255) / 256, 256>>>(logits);
    loss_kernel<<<2048, 256>>>(nbr, labels, out);
}

// round 7
// speedup vs baseline: 1.1740x; 1.1740x over previous
#include <cuda_runtime.h>
#include <cuda_fp16.h>

#define NPTS 500000
#define NCLS 20
#define NK   16

// fp16 probs table: 500000*20*2B = 20 MB (L2-resident). Device globals (no alloc).
__device__ __half g_probs_h[(size_t)NPTS * NCLS];
__device__ float  g_acc[2];    // [0]=sum of mean_dist over valid pts, [1]=valid count
__device__ int    g_done = 0;

// Kernel 1: softmax (fp32 in, fp16 out) + accumulator reset.
__global__ void softmax_kernel(const float* __restrict__ logits) {
    if (blockIdx.x == 0 && threadIdx.x == 0) {
        g_acc[0] = 0.0f;
        g_acc[1] = 0.0f;
        g_done   = 0;
    }
    int n = blockIdx.x * blockDim.x + threadIdx.x;
    if (n >= NPTS) return;
    const float4* src = reinterpret_cast<const float4*>(logits + (size_t)n * NCLS);
    float4 v[5];
#pragma unroll
    for (int i = 0; i < 5; i++) v[i] = src[i];
    float* f = reinterpret_cast<float*>(v);
    float m = f[0];
#pragma unroll
    for (int i = 1; i < NCLS; i++) m = fmaxf(m, f[i]);
    float s = 0.0f;
#pragma unroll
    for (int i = 0; i < NCLS; i++) { f[i] = __expf(f[i] - m); s += f[i]; }
    float inv = 1.0f / s;
    __half2* dst = reinterpret_cast<__half2*>(g_probs_h + (size_t)n * NCLS);
#pragma unroll
    for (int i = 0; i < 10; i++)
        dst[i] = __floats2half2_rn(f[2 * i] * inv, f[2 * i + 1] * inv);
}

// Kernel 2: warp-per-2-points gather (MLP x2), half2 math.
// Index load uses the FULL warp: lanes 0-15 hold point0's 16 neighbor indices,
// lanes 16-31 hold point1's. One coalesced LDG + one ballot per 2 points.
// Gather lane layout: grp = lane>>3 (0..3), sub = lane&7; lanes with sub<5 own
// classes [4*sub,4*sub+4) as uint2 (two half2). Step s: group g handles
// neighbor 4*s+g -> one LDG.64 instruction gathers 4 neighbor rows.
__global__ void loss_kernel(const int* __restrict__ nbr,
                            const int* __restrict__ labels,
                            float* __restrict__ out) {
    const int lane = threadIdx.x & 31;
    const int warpInBlock = threadIdx.x >> 5;
    const int warpsPerBlock = blockDim.x >> 5;
    const int gwarp = blockIdx.x * warpsPerBlock + warpInBlock;
    const int totalWarps = gridDim.x * warpsPerBlock;
    const int grp = lane >> 3;
    const int sub = lane & 7;
    const bool active = (sub < 5);
    const int laneOff = 4 * sub;

    float accTot = 0.0f;
    float cnt    = 0.0f;
    const __half2 z2 = __float2half2_rn(0.f);

    for (int n0 = gwarp; n0 < NPTS; n0 += 2 * totalWarps) {
        const int n1 = n0 + totalWarps;
        const bool has1 = (n1 < NPTS);

        // ---- front loads for both points ----
        int lab0 = labels[n0];
        int lab1 = has1 ? labels[n1] : -1;

        // Full-warp neighbor-index load: lane<16 -> point0, lane>=16 -> point1
        int myPt = (lane < 16) ? n0 : n1;
        int myIdx = -1;
        if (myPt < NPTS) myIdx = nbr[myPt * NK + (lane & 15)];

        __half2 pa0 = z2, pb0 = z2, pa1 = z2, pb1 = z2;
        if (active) {
            uint2 pw0 = *reinterpret_cast<const uint2*>(g_probs_h + n0 * NCLS + laneOff);
            pa0 = *reinterpret_cast<__half2*>(&pw0.x);
            pb0 = *reinterpret_cast<__half2*>(&pw0.y);
            if (has1) {
                uint2 pw1 = *reinterpret_cast<const uint2*>(g_probs_h + n1 * NCLS + laneOff);
                pa1 = *reinterpret_cast<__half2*>(&pw1.x);
                pb1 = *reinterpret_cast<__half2*>(&pw1.y);
            }
        }

        // One ballot covers both points
        unsigned vm = __ballot_sync(0xFFFFFFFFu, myIdx >= 0);
        int nv0 = __popc(vm & 0xFFFFu);
        int nv1 = __popc(vm >> 16);
        bool do0 = (lab0 != -1) && nv0 > 0;
        bool do1 = has1 && (lab1 != -1) && nv1 > 0;

        // ---- all 8 shuffles, then all 8 gathers in flight ----
        int q0[4], q1[4];
#pragma unroll
        for (int s = 0; s < 4; s++) {
            q0[s] = __shfl_sync(0xFFFFFFFFu, myIdx, 4 * s + grp);
            q1[s] = __shfl_sync(0xFFFFFFFFu, myIdx, 16 + 4 * s + grp);
        }

        __half2 acc0 = z2, acc1 = z2;
#pragma unroll
        for (int s = 0; s < 4; s++) {
            if (do0 && active && q0[s] >= 0) {
                uint2 qw = *reinterpret_cast<const uint2*>(
                    g_probs_h + q0[s] * NCLS + laneOff);
                __half2 da = __hsub2(pa0, *reinterpret_cast<__half2*>(&qw.x));
                __half2 db = __hsub2(pb0, *reinterpret_cast<__half2*>(&qw.y));
                acc0 = __hfma2(da, da, acc0);
                acc0 = __hfma2(db, db, acc0);
            }
            if (do1 && active && q1[s] >= 0) {
                uint2 qw = *reinterpret_cast<const uint2*>(
                    g_probs_h + q1[s] * NCLS + laneOff);
                __half2 da = __hsub2(pa1, *reinterpret_cast<__half2*>(&qw.x));
                __half2 db = __hsub2(pb1, *reinterpret_cast<__half2*>(&qw.y));
                acc1 = __hfma2(da, da, acc1);
                acc1 = __hfma2(db, db, acc1);
            }
        }

        if (do0) {
            float2 af = __half22float2(acc0);
            accTot = fmaf(af.x + af.y, __frcp_rn((float)nv0), accTot);
        }
        if (do1) {
            float2 af = __half22float2(acc1);
            accTot = fmaf(af.x + af.y, __frcp_rn((float)nv1), accTot);
        }
        cnt += (lab0 != -1 ? 1.0f : 0.0f) + (has1 && lab1 != -1 ? 1.0f : 0.0f);
    }

    // One butterfly reduce per warp
#pragma unroll
    for (int o = 16; o > 0; o >>= 1)
        accTot += __shfl_xor_sync(0xFFFFFFFFu, accTot, o);

    // Block reduce -> one atomic pair per block
    __shared__ float sSum[32];
    __shared__ float sCnt[32];
    if (lane == 0) { sSum[warpInBlock] = accTot; sCnt[warpInBlock] = cnt; }
    __syncthreads();
    if (threadIdx.x == 0) {
        float bs = 0.0f, bc = 0.0f;
        for (int w = 0; w < warpsPerBlock; w++) { bs += sSum[w]; bc += sCnt[w]; }
        atomicAdd(&g_acc[0], bs);
        atomicAdd(&g_acc[1], bc);
        __threadfence();
        int t = atomicAdd(&g_done, 1);
        if (t == gridDim.x - 1) {
            out[0] = g_acc[0] / fmaxf(g_acc[1], 1.0f);  // LOSS_WEIGHT = 1.0
            g_done = 0;
        }
    }
}

extern "C" void kernel_launch(void* const* d_in, const int* in_sizes, int n_in,
                              void* d_out, int out_size) {
    const float* logits = nullptr;
    const int*   nbr    = nullptr;
    const int*   labels = nullptr;
    for (int i = 0; i < n_in; i++) {
        if (in_sizes[i] == NPTS * NCLS)    logits = (const float*)d_in[i];
        else if (in_sizes[i] == NPTS * NK) nbr    = (const int*)d_in[i];
        else if (in_sizes[i] == NPTS)      labels = (const int*)d_in[i];
    }
    float* out = (float*)d_out;

    softmax_kernel<<<(NPTS + 255) / 256, 256>>>(logits);
    loss_kernel<<<2048, 256>>>(nbr, labels, out);
}